// round 2
// baseline (speedup 1.0000x reference)
#include <cuda_runtime.h>

#define ALPHA 100.0f
#define MG 5

static constexpr int B = 32, C = 3, H = 512, W = 512;
static constexpr int HW = H * W;
static constexpr int GROUPS_PER_B = H * (W / 8);   // 8-pixel groups per sample = 32768
static constexpr float INV_N = 1.0f / (float(B) * C * H * W);

__global__ void zero_out_kernel(float* out) { out[0] = 0.0f; }

__device__ __forceinline__ float pix_w(int p, int lo, int hi, int ty, bool cond)
{
    const int tx = min(p - lo + 6, hi + 5 - p);       // >=6 inside, 1..5 in ramp
    const int fmin = min(min(tx, ty), 5);             // clamped band value
    if (cond)
        return (fmin > 0) ? (float)fmin * (ALPHA / (float)MG) : 1.0f;
    return (tx >= 6 && ty >= 6) ? ALPHA : 1.0f;
}

__global__ void __launch_bounds__(256)
mae_bbox_kernel(const float* __restrict__ x,
                const float* __restrict__ y,
                const int*   __restrict__ bbox,
                float*       __restrict__ out)
{
    const int b = blockIdx.y;

    // hoisted per-sample bbox reduction (uniform across block)
    const int* bb = bbox + b * 8;
    const int xmin = min(min(bb[0], bb[2]), min(bb[4], bb[6]));
    const int xmax = max(max(bb[0], bb[2]), max(bb[4], bb[6]));
    const int ymin = min(min(bb[1], bb[3]), min(bb[5], bb[7]));
    const int ymax = max(max(bb[1], bb[3]), max(bb[5], bb[7]));
    const bool cond = (xmin - MG > 0) && (xmax + MG < W) &&
                      (ymin - MG > 0) && (ymax + MG < H);

    const float* xb = x + b * (C * HW);
    const float* yb = y + b * (C * HW);

    float a0 = 0.f, a1 = 0.f, a2 = 0.f, a3 = 0.f;

    const int nthr = gridDim.x * blockDim.x;          // threads serving this b
    for (int g = blockIdx.x * blockDim.x + threadIdx.x; g < GROUPS_PER_B; g += nthr)
    {
        const int h  = g >> 6;                        // row (64 groups per row)
        const int x0 = (g & 63) << 3;                 // first of 8 pixels

        const int ty = min(h - ymin + 6, ymax + 5 - h);

        float w[8];
        #pragma unroll
        for (int i = 0; i < 8; i++)
            w[i] = pix_w(x0 + i, xmin, xmax, ty, cond);

        const int base = h * W + x0;
        #pragma unroll
        for (int c = 0; c < C; c++) {
            const float4 xa = *reinterpret_cast<const float4*>(xb + base + c * HW);
            const float4 xc = *reinterpret_cast<const float4*>(xb + base + c * HW + 4);
            const float4 ya = *reinterpret_cast<const float4*>(yb + base + c * HW);
            const float4 yc = *reinterpret_cast<const float4*>(yb + base + c * HW + 4);
            a0 += fabsf(xa.x - ya.x) * w[0];
            a1 += fabsf(xa.y - ya.y) * w[1];
            a2 += fabsf(xa.z - ya.z) * w[2];
            a3 += fabsf(xa.w - ya.w) * w[3];
            a0 += fabsf(xc.x - yc.x) * w[4];
            a1 += fabsf(xc.y - yc.y) * w[5];
            a2 += fabsf(xc.z - yc.z) * w[6];
            a3 += fabsf(xc.w - yc.w) * w[7];
        }
    }

    float acc = (a0 + a1) + (a2 + a3);

    // warp reduce
    #pragma unroll
    for (int o = 16; o > 0; o >>= 1)
        acc += __shfl_down_sync(0xffffffff, acc, o);

    __shared__ float sm[8];
    const int lane = threadIdx.x & 31;
    const int wid  = threadIdx.x >> 5;
    if (lane == 0) sm[wid] = acc;
    __syncthreads();

    if (wid == 0) {
        acc = (lane < 8) ? sm[lane] : 0.0f;
        #pragma unroll
        for (int o = 4; o > 0; o >>= 1)
            acc += __shfl_down_sync(0xffffffff, acc, o);
        if (lane == 0)
            atomicAdd(out, acc * INV_N);
    }
}

extern "C" void kernel_launch(void* const* d_in, const int* in_sizes, int n_in,
                              void* d_out, int out_size)
{
    const float* x    = (const float*)d_in[0];
    const float* y    = (const float*)d_in[1];
    const int*   bbox = (const int*)d_in[2];
    float* out = (float*)d_out;

    zero_out_kernel<<<1, 1>>>(out);
    mae_bbox_kernel<<<dim3(37, 32), 256>>>(x, y, bbox, out);
}